// round 16
// baseline (speedup 1.0000x reference)
#include <cuda_runtime.h>
#include <cstdint>
#include <cstddef>

#define THREADS 256
#define ITEMS   16
#define TILE_N  (THREADS * ITEMS)   /* 4096 */
#define TILES   1024                /* per curve: 4194304 / 4096 */
#define NWARP   (THREADS / 32)
#define SKEW    17
#define AGG_PER_THREAD (TILES / THREADS)   /* 4 */

// ---------------- inter-kernel state (device globals; no allocation) --------
__device__ float4 g_agg[2 * TILES];   // per-tile (dTheta, dx, dy) at base angle 0

// ---------------- streaming store -------------------------------------------
static __device__ __forceinline__ void stcs4(float4* p, float4 v) {
    asm volatile("st.global.cs.v4.f32 [%0], {%1,%2,%3,%4};"
                 :: "l"(p), "f"(v.x), "f"(v.y), "f"(v.z), "f"(v.w) : "memory");
}

// ---------------- polynomial sincos (float-exact for |a| <= ~0.6) ----------
static __device__ __forceinline__ void poly_sincos(float a, float* s, float* c) {
    float x2 = a * a;
    float st = fmaf(x2, -1.984126984e-4f, 8.333333333e-3f);
    st = fmaf(x2, st, -1.666666667e-1f);
    st = fmaf(x2, st, 1.0f);
    *s = a * st;
    float ct = fmaf(x2, 2.480158730e-5f, -1.388888889e-3f);
    ct = fmaf(x2, ct, 4.166666667e-2f);
    ct = fmaf(x2, ct, -5.0e-1f);
    *c = fmaf(x2, ct, 1.0f);
}

// ---------------- scan helpers ---------------------------------------------
__device__ __forceinline__ float warp_iscan(float v, int lane) {
#pragma unroll
    for (int o = 1; o < 32; o <<= 1) {
        float n = __shfl_up_sync(0xffffffffu, v, o);
        if (lane >= o) v += n;
    }
    return v;
}
__device__ __forceinline__ float2 warp_iscan2(float2 v, int lane) {
#pragma unroll
    for (int o = 1; o < 32; o <<= 1) {
        float nx = __shfl_up_sync(0xffffffffu, v.x, o);
        float ny = __shfl_up_sync(0xffffffffu, v.y, o);
        if (lane >= o) { v.x += nx; v.y += ny; }
    }
    return v;
}

template <int NW>
__device__ __forceinline__ float block_escan(float v, float* sw, float& total,
                                             int tid, int lane, int w) {
    float inc = warp_iscan(v, lane);
    if (lane == 31) sw[w] = inc;
    __syncthreads();
    if (tid < 32) {
        float x = (lane < NW) ? sw[lane] : 0.0f;
        x = warp_iscan(x, lane);
        if (lane < NW) sw[lane] = x;
    }
    __syncthreads();
    float off = (w > 0) ? sw[w - 1] : 0.0f;
    total = sw[NW - 1];
    return off + (inc - v);
}
template <int NW>
__device__ __forceinline__ float2 block_escan2(float2 v, float2* sw, float2& total,
                                               int tid, int lane, int w) {
    float2 inc = warp_iscan2(v, lane);
    if (lane == 31) sw[w] = inc;
    __syncthreads();
    if (tid < 32) {
        float2 x = (lane < NW) ? sw[lane] : make_float2(0.f, 0.f);
        x = warp_iscan2(x, lane);
        if (lane < NW) sw[lane] = x;
    }
    __syncthreads();
    float2 off = (w > 0) ? sw[w - 1] : make_float2(0.f, 0.f);
    total = sw[NW - 1];
    return make_float2(off.x + (inc.x - v.x), off.y + (inc.y - v.y));
}

// ============================================================================
// K1: per-tile aggregates — R10 config (256 thr x 16 items, best measured)
// ============================================================================
__global__ void __launch_bounds__(THREADS, 6)
tile_agg_kernel(const float* __restrict__ vecA,
                const float* __restrict__ vecB,
                const float* __restrict__ dlp)
{
    __shared__ float  sT[NWARP];
    __shared__ float2 sXY[NWARP];

    const int curve = blockIdx.y;
    const int tile  = blockIdx.x;
    const float* __restrict__ vec = curve ? vecB : vecA;
    const float dl = dlp[0];

    const int tid  = threadIdx.x;
    const int lane = tid & 31;
    const int w    = tid >> 5;
    const int base = tile * TILE_N + tid * ITEMS;

    float v[ITEMS];
    {
        const float4* v4 = reinterpret_cast<const float4*>(vec + base);
#pragma unroll
        for (int k = 0; k < ITEMS / 4; k++) {
            float4 q = v4[k];
            v[4 * k + 0] = q.x; v[4 * k + 1] = q.y;
            v[4 * k + 2] = q.z; v[4 * k + 3] = q.w;
        }
    }
    float tot = 0.f;
#pragma unroll
    for (int k = 0; k < ITEMS; k += 4)
        tot += (v[k] + v[k + 1]) + (v[k + 2] + v[k + 3]);

    float totT;
    float te = block_escan<NWARP>(tot, sT, totT, tid, lane, w);

    // complex-rotation chain: z = dl*e^{i(te+cumsum v)}; |v_k| tiny so
    // e^{iv} = (1 - v^2/2, v) is float-exact.
    float sn, cs;
    poly_sincos(te, &sn, &cs);
    float zx = dl * cs, zy = dl * sn;
    float Cx = 0.f, Cy = 0.f;
#pragma unroll
    for (int k = 0; k < ITEMS; k++) {
        float vk = v[k];
        float ec = fmaf(-0.5f * vk, vk, 1.0f);
        float nx = fmaf(zx, ec, -(zy * vk));
        float ny = fmaf(zy, ec,  (zx * vk));
        zx = nx; zy = ny;
        Cx += zx; Cy += zy;
    }
#pragma unroll
    for (int o = 16; o > 0; o >>= 1) {
        Cx += __shfl_xor_sync(0xffffffffu, Cx, o);
        Cy += __shfl_xor_sync(0xffffffffu, Cy, o);
    }
    if (lane == 0) sXY[w] = make_float2(Cx, Cy);
    __syncthreads();
    if (tid == 0) {
        float sx = 0.f, sy = 0.f;
#pragma unroll
        for (int i = 0; i < NWARP; i++) { sx += sXY[i].x; sy += sXY[i].y; }
        g_agg[curve * TILES + tile] = make_float4(totT, sx, sy, 0.f);
    }
}

// ============================================================================
// K2 is GONE: each K3 block computes its own tile prefix from g_agg
// (masked rotate-reduce over entries j < tile; MUFU sincos — accuracy ~1e-6).
// ============================================================================

#define OFF_STAGE 0
#define SZ_STAGE  (THREADS * SKEW * 8)       /* 34816 */
#define OFF_EXY   (OFF_STAGE + SZ_STAGE)
#define SZ_EXY    (THREADS * 8)
#define OFF_ST    (OFF_EXY + SZ_EXY)
#define SZ_ST     (NWARP * 4)
#define OFF_SXY   (OFF_ST + SZ_ST)
#define SZ_SXY    (NWARP * 8)
#define OFF_RED   (OFF_SXY + SZ_SXY)
#define SZ_RED    (NWARP * 12)               /* (st,sx,sy) per warp */
#define OFF_PRE   (OFF_RED + SZ_RED)
#define SZ_PRE    32
#define SMEM_BYTES (OFF_PRE + SZ_PRE)        /* ~37KB -> 6 blocks/SM */

__global__ void __launch_bounds__(THREADS, 6)
curve_apply_kernel(const float* __restrict__ vecA,
                   const float* __restrict__ vecB,
                   const float* __restrict__ the0A,
                   const float* __restrict__ the0B,
                   const float* __restrict__ startA,
                   const float* __restrict__ startB,
                   const float* __restrict__ dlp,
                   float* __restrict__ out, int n)
{
    extern __shared__ char smembuf[];
    float2* sStage = (float2*)(smembuf + OFF_STAGE);
    float2* sExy   = (float2*)(smembuf + OFF_EXY);
    float*  sT     = (float*) (smembuf + OFF_ST);
    float2* sXY    = (float2*)(smembuf + OFF_SXY);
    float3* sRed   = (float3*)(smembuf + OFF_RED);
    float*  sPre   = (float*) (smembuf + OFF_PRE);

    const int curve = blockIdx.y;
    const int tile  = blockIdx.x;
    const float* __restrict__ vec = curve ? vecB : vecA;
    const float th0 = curve ? the0B[0] : the0A[0];
    const float stx = curve ? startB[0] : startA[0];
    const float sty = curve ? startB[1] : startA[1];
    const float dl  = dlp[0];
    float* outc = out + (size_t)curve * (size_t)2 * (size_t)(n + 1);

    const int tid  = threadIdx.x;
    const int lane = tid & 31;
    const int w    = tid >> 5;
    const int base = tile * TILE_N + tid * ITEMS;

    // issue the main vec loads FIRST so they overlap the prefix prologue
    float v[ITEMS];
    {
        const float4* v4 = reinterpret_cast<const float4*>(vec + base);
#pragma unroll
        for (int k = 0; k < ITEMS / 4; k++) {
            float4 q = v4[k];
            v[4 * k + 0] = q.x; v[4 * k + 1] = q.y;
            v[4 * k + 2] = q.z; v[4 * k + 3] = q.w;
        }
    }

    // ---- inline tile prefix (replaces K2) ---------------------------------
    // thread t handles g_agg entries [4t, 4t+4); masked by j < tile.
    {
        const float4* agg = g_agg + curve * TILES + tid * AGG_PER_THREAD;
        float4 a0 = agg[0], a1 = agg[1], a2 = agg[2], a3 = agg[3];
        float thsum = (a0.x + a1.x) + (a2.x + a3.x);
        float dummy;
        float ang = block_escan<NWARP>(thsum, sT, dummy, tid, lane, w);

        float st = 0.f, sx = 0.f, sy = 0.f;
        int j = tid * AGG_PER_THREAD;
#pragma unroll
        for (int e = 0; e < AGG_PER_THREAD; e++) {
            float4 a = (e == 0) ? a0 : (e == 1) ? a1 : (e == 2) ? a2 : a3;
            if (j + e < tile) {
                float s, c;
                __sincosf(ang, &s, &c);
                sx = fmaf(c, a.y, fmaf(-s, a.z, sx));
                sy = fmaf(s, a.y, fmaf( c, a.z, sy));
                st += a.x;
            }
            ang += a.x;
        }
#pragma unroll
        for (int o = 16; o > 0; o >>= 1) {
            st += __shfl_xor_sync(0xffffffffu, st, o);
            sx += __shfl_xor_sync(0xffffffffu, sx, o);
            sy += __shfl_xor_sync(0xffffffffu, sy, o);
        }
        if (lane == 0) sRed[w] = make_float3(st, sx, sy);
        __syncthreads();
        if (tid == 0) {
            float pT = 0.f, pX = 0.f, pY = 0.f;
#pragma unroll
            for (int i = 0; i < NWARP; i++) {
                pT += sRed[i].x; pX += sRed[i].y; pY += sRed[i].z;
            }
            float s0, c0, sB, cB;
            sincosf(th0, &s0, &c0);
            sincosf(th0 + pT, &sB, &cB);
            sPre[0] = stx + c0 * pX - s0 * pY;   // bx
            sPre[1] = sty + s0 * pX + c0 * pY;   // by
            sPre[2] = cB;
            sPre[3] = sB;
        }
        __syncthreads();   // sT free for reuse; sPre not yet read
    }

    float tot = 0.f;
#pragma unroll
    for (int k = 0; k < ITEMS; k += 4)
        tot += (v[k] + v[k + 1]) + (v[k + 2] + v[k + 3]);

    float totT;
    float te = block_escan<NWARP>(tot, sT, totT, tid, lane, w);

    float sn, cs;
    poly_sincos(te, &sn, &cs);
    float zx = dl * cs, zy = dl * sn;
    float Cx = 0.f, Cy = 0.f;
    // curve 0 stages EXCLUSIVE local cumsum, curve 1 INCLUSIVE
#pragma unroll
    for (int k = 0; k < ITEMS; k++) {
        float vk = v[k];
        float ec = fmaf(-0.5f * vk, vk, 1.0f);
        float nx = fmaf(zx, ec, -(zy * vk));
        float ny = fmaf(zy, ec,  (zx * vk));
        zx = nx; zy = ny;
        float px = Cx, py = Cy;
        Cx += zx; Cy += zy;
        sStage[tid * SKEW + k] = curve ? make_float2(Cx, Cy)
                                       : make_float2(px, py);
    }
    float2 tot2;
    float2 e2 = block_escan2<NWARP>(make_float2(Cx, Cy), sXY, tot2, tid, lane, w);
    sExy[tid] = e2;
    __syncthreads();

    const float bx = sPre[0], by = sPre[1], cB = sPre[2], sB = sPre[3];

    float4* dst4 = reinterpret_cast<float4*>(
        outc + 2 * (size_t)tile * TILE_N + (curve ? 2 : 0));
#pragma unroll
    for (int k = 0; k < ITEMS / 2; k++) {
        int p  = k * THREADS + tid;        // float4 index = 2 points
        int wt = p >> 3;
        int kk = (p & 7) * 2;
        float2 l0 = sStage[wt * SKEW + kk];
        float2 l1 = sStage[wt * SKEW + kk + 1];
        float2 e  = sExy[wt];
        float ux0 = e.x + l0.x, uy0 = e.y + l0.y;
        float ux1 = e.x + l1.x, uy1 = e.y + l1.y;
        float4 o;
        o.x = fmaf(cB, ux0, fmaf(-sB, uy0, bx));
        o.y = fmaf(sB, ux0, fmaf( cB, uy0, by));
        o.z = fmaf(cB, ux1, fmaf(-sB, uy1, bx));
        o.w = fmaf(sB, ux1, fmaf( cB, uy1, by));
        stcs4(&dst4[p], o);
    }

    // fix-ups: curve0 last row (N); curve1 first row (0)
    if (curve == 0 && tile == TILES - 1 && tid == THREADS - 1) {
        float ux = e2.x + Cx, uy = e2.y + Cy;
        outc[2 * (size_t)n + 0] = fmaf(cB, ux, fmaf(-sB, uy, bx));
        outc[2 * (size_t)n + 1] = fmaf(sB, ux, fmaf( cB, uy, by));
    }
    if (curve == 1 && tile == 0 && tid == 0) {
        outc[0] = stx; outc[1] = sty;
    }
}

// ---------------- launch ----------------------------------------------------
extern "C" void kernel_launch(void* const* d_in, const int* in_sizes, int n_in,
                              void* d_out, int out_size) {
    const float* vec   = (const float*)d_in[0];
    const float* vec2  = (const float*)d_in[1];
    const float* the0  = (const float*)d_in[2];
    const float* the02 = (const float*)d_in[3];
    const float* PS    = (const float*)d_in[4];
    const float* PE    = (const float*)d_in[5];
    const float* dl    = (const float*)d_in[6];
    float* out = (float*)d_out;

    int n = in_sizes[0];

    cudaFuncSetAttribute(curve_apply_kernel,
                         cudaFuncAttributeMaxDynamicSharedMemorySize, SMEM_BYTES);

    tile_agg_kernel<<<dim3(TILES, 2), THREADS>>>(vec, vec2, dl);
    curve_apply_kernel<<<dim3(TILES, 2), THREADS, SMEM_BYTES>>>(
        vec, vec2, the0, the02, PS, PE, dl, out, n);
}

// round 17
// speedup vs baseline: 1.0856x; 1.0856x over previous
#include <cuda_runtime.h>
#include <cstdint>
#include <cstddef>

#define THREADS 256
#define ITEMS   16
#define TILE_N  (THREADS * ITEMS)   /* 4096 */
#define TILES   1024                /* per curve: 4194304 / 4096 */
#define NWARP   (THREADS / 32)
#define SKEW    17
#define APT     (TILES / THREADS)   /* 4 agg entries per thread in prefix */

// ---------------- inter-kernel state (device globals; no allocation) --------
__device__ float4 g_agg[2 * TILES];   // per-tile (dTheta, dx, dy) at base angle 0
__device__ float4 g_pre[2 * TILES];   // per-tile exclusive prefix (theta, x, y)
__device__ int    g_ctr[2];           // last-block-done counters (self-resetting)

// ---------------- streaming store -------------------------------------------
static __device__ __forceinline__ void stcs4(float4* p, float4 v) {
    asm volatile("st.global.cs.v4.f32 [%0], {%1,%2,%3,%4};"
                 :: "l"(p), "f"(v.x), "f"(v.y), "f"(v.z), "f"(v.w) : "memory");
}

// ---------------- polynomial sincos (float-exact for |a| <= ~0.6) ----------
static __device__ __forceinline__ void poly_sincos(float a, float* s, float* c) {
    float x2 = a * a;
    float st = fmaf(x2, -1.984126984e-4f, 8.333333333e-3f);
    st = fmaf(x2, st, -1.666666667e-1f);
    st = fmaf(x2, st, 1.0f);
    *s = a * st;
    float ct = fmaf(x2, 2.480158730e-5f, -1.388888889e-3f);
    ct = fmaf(x2, ct, 4.166666667e-2f);
    ct = fmaf(x2, ct, -5.0e-1f);
    *c = fmaf(x2, ct, 1.0f);
}

// ---------------- scan helpers ---------------------------------------------
__device__ __forceinline__ float warp_iscan(float v, int lane) {
#pragma unroll
    for (int o = 1; o < 32; o <<= 1) {
        float n = __shfl_up_sync(0xffffffffu, v, o);
        if (lane >= o) v += n;
    }
    return v;
}
__device__ __forceinline__ float2 warp_iscan2(float2 v, int lane) {
#pragma unroll
    for (int o = 1; o < 32; o <<= 1) {
        float nx = __shfl_up_sync(0xffffffffu, v.x, o);
        float ny = __shfl_up_sync(0xffffffffu, v.y, o);
        if (lane >= o) { v.x += nx; v.y += ny; }
    }
    return v;
}

template <int NW>
__device__ __forceinline__ float block_escan(float v, float* sw, float& total,
                                             int tid, int lane, int w) {
    float inc = warp_iscan(v, lane);
    if (lane == 31) sw[w] = inc;
    __syncthreads();
    if (tid < 32) {
        float x = (lane < NW) ? sw[lane] : 0.0f;
        x = warp_iscan(x, lane);
        if (lane < NW) sw[lane] = x;
    }
    __syncthreads();
    float off = (w > 0) ? sw[w - 1] : 0.0f;
    total = sw[NW - 1];
    return off + (inc - v);
}
template <int NW>
__device__ __forceinline__ float2 block_escan2(float2 v, float2* sw, float2& total,
                                               int tid, int lane, int w) {
    float2 inc = warp_iscan2(v, lane);
    if (lane == 31) sw[w] = inc;
    __syncthreads();
    if (tid < 32) {
        float2 x = (lane < NW) ? sw[lane] : make_float2(0.f, 0.f);
        x = warp_iscan2(x, lane);
        if (lane < NW) sw[lane] = x;
    }
    __syncthreads();
    float2 off = (w > 0) ? sw[w - 1] : make_float2(0.f, 0.f);
    total = sw[NW - 1];
    return make_float2(off.x + (inc.x - v.x), off.y + (inc.y - v.y));
}

// ============================================================================
// K1: per-tile aggregates (R10 body) + last-block-done tile-prefix scan.
// The final block per curve computes the whole prefix (once), replacing K2.
// ============================================================================
__global__ void __launch_bounds__(THREADS, 6)
tile_agg_kernel(const float* __restrict__ vecA,
                const float* __restrict__ vecB,
                const float* __restrict__ dlp)
{
    __shared__ float  sT[NWARP];
    __shared__ float2 sXY[NWARP];
    __shared__ int    sIsLast;

    const int curve = blockIdx.y;
    const int tile  = blockIdx.x;
    const float* __restrict__ vec = curve ? vecB : vecA;
    const float dl = dlp[0];

    const int tid  = threadIdx.x;
    const int lane = tid & 31;
    const int w    = tid >> 5;
    const int base = tile * TILE_N + tid * ITEMS;

    float v[ITEMS];
    {
        const float4* v4 = reinterpret_cast<const float4*>(vec + base);
#pragma unroll
        for (int k = 0; k < ITEMS / 4; k++) {
            float4 q = v4[k];
            v[4 * k + 0] = q.x; v[4 * k + 1] = q.y;
            v[4 * k + 2] = q.z; v[4 * k + 3] = q.w;
        }
    }
    float tot = 0.f;
#pragma unroll
    for (int k = 0; k < ITEMS; k += 4)
        tot += (v[k] + v[k + 1]) + (v[k + 2] + v[k + 3]);

    float totT;
    float te = block_escan<NWARP>(tot, sT, totT, tid, lane, w);

    // complex-rotation chain: z = dl*e^{i(te+cumsum v)}; |v_k| tiny so
    // e^{iv} = (1 - v^2/2, v) is float-exact.
    float sn, cs;
    poly_sincos(te, &sn, &cs);
    float zx = dl * cs, zy = dl * sn;
    float Cx = 0.f, Cy = 0.f;
#pragma unroll
    for (int k = 0; k < ITEMS; k++) {
        float vk = v[k];
        float ec = fmaf(-0.5f * vk, vk, 1.0f);
        float nx = fmaf(zx, ec, -(zy * vk));
        float ny = fmaf(zy, ec,  (zx * vk));
        zx = nx; zy = ny;
        Cx += zx; Cy += zy;
    }
#pragma unroll
    for (int o = 16; o > 0; o >>= 1) {
        Cx += __shfl_xor_sync(0xffffffffu, Cx, o);
        Cy += __shfl_xor_sync(0xffffffffu, Cy, o);
    }
    if (lane == 0) sXY[w] = make_float2(Cx, Cy);
    __syncthreads();
    if (tid == 0) {
        float sx = 0.f, sy = 0.f;
#pragma unroll
        for (int i = 0; i < NWARP; i++) { sx += sXY[i].x; sy += sXY[i].y; }
        g_agg[curve * TILES + tile] = make_float4(totT, sx, sy, 0.f);
        __threadfence();                        // release g_agg write
        int c = atomicAdd(&g_ctr[curve], 1);
        sIsLast = (c == TILES - 1);
    }
    __syncthreads();
    if (!sIsLast) return;

    // ---- last block of this curve: compute the full tile prefix (was K2) ---
    __threadfence();                            // acquire all g_agg writes

    const float4* agg = g_agg + curve * TILES;
    float4 a0 = agg[tid * APT + 0];
    float4 a1 = agg[tid * APT + 1];
    float4 a2 = agg[tid * APT + 2];
    float4 a3 = agg[tid * APT + 3];

    float thsum = (a0.x + a1.x) + (a2.x + a3.x);
    float dummy;
    float ang = block_escan<NWARP>(thsum, sT, dummy, tid, lane, w);

    // rotate each entry's displacement by its exclusive angle (precise trig)
    float th0e = ang;
    float th1e = th0e + a0.x;
    float th2e = th1e + a1.x;
    float th3e = th2e + a2.x;
    float s0, c0, s1, c1, s2, c2, s3, c3;
    sincosf(th0e, &s0, &c0);
    sincosf(th1e, &s1, &c1);
    sincosf(th2e, &s2, &c2);
    sincosf(th3e, &s3, &c3);
    float2 r0 = make_float2(c0 * a0.y - s0 * a0.z, s0 * a0.y + c0 * a0.z);
    float2 r1 = make_float2(c1 * a1.y - s1 * a1.z, s1 * a1.y + c1 * a1.z);
    float2 r2 = make_float2(c2 * a2.y - s2 * a2.z, s2 * a2.y + c2 * a2.z);
    float2 r3 = make_float2(c3 * a3.y - s3 * a3.z, s3 * a3.y + c3 * a3.z);

    float2 lsum = make_float2((r0.x + r1.x) + (r2.x + r3.x),
                              (r0.y + r1.y) + (r2.y + r3.y));
    float2 tot2;
    float2 off = block_escan2<NWARP>(lsum, sXY, tot2, tid, lane, w);

    float4* pre = g_pre + curve * TILES + tid * APT;
    float rx = off.x, ry = off.y;
    pre[0] = make_float4(th0e, rx, ry, 0.f);  rx += r0.x; ry += r0.y;
    pre[1] = make_float4(th1e, rx, ry, 0.f);  rx += r1.x; ry += r1.y;
    pre[2] = make_float4(th2e, rx, ry, 0.f);  rx += r2.x; ry += r2.y;
    pre[3] = make_float4(th3e, rx, ry, 0.f);

    if (tid == 0) g_ctr[curve] = 0;             // self-reset for graph replay
}

// ============================================================================
// K3: apply — identical to R10/R15 best: staging + aligned float4 st.cs
//   curve 0: rows [t*TILE_N, (t+1)*TILE_N)   (exclusive staging)
//   curve 1: rows [t*TILE_N+1, (t+1)*TILE_N] (inclusive staging; restores
//            16B alignment of the curve-1 base)
// ============================================================================
#define OFF_STAGE 0
#define SZ_STAGE  (THREADS * SKEW * 8)       /* 34816 */
#define OFF_EXY   (OFF_STAGE + SZ_STAGE)
#define SZ_EXY    (THREADS * 8)
#define OFF_ST    (OFF_EXY + SZ_EXY)
#define SZ_ST     (NWARP * 4)
#define OFF_SXY   (OFF_ST + SZ_ST)
#define SZ_SXY    (NWARP * 8)
#define OFF_PRE   (OFF_SXY + SZ_SXY)
#define SZ_PRE    32
#define SMEM_BYTES (OFF_PRE + SZ_PRE)        /* ~37KB -> 6 blocks/SM */

__global__ void __launch_bounds__(THREADS, 6)
curve_apply_kernel(const float* __restrict__ vecA,
                   const float* __restrict__ vecB,
                   const float* __restrict__ the0A,
                   const float* __restrict__ the0B,
                   const float* __restrict__ startA,
                   const float* __restrict__ startB,
                   const float* __restrict__ dlp,
                   float* __restrict__ out, int n)
{
    extern __shared__ char smembuf[];
    float2* sStage = (float2*)(smembuf + OFF_STAGE);
    float2* sExy   = (float2*)(smembuf + OFF_EXY);
    float*  sT     = (float*) (smembuf + OFF_ST);
    float2* sXY    = (float2*)(smembuf + OFF_SXY);
    float*  sPre   = (float*) (smembuf + OFF_PRE);

    const int curve = blockIdx.y;
    const int tile  = blockIdx.x;
    const float* __restrict__ vec = curve ? vecB : vecA;
    const float th0 = curve ? the0B[0] : the0A[0];
    const float stx = curve ? startB[0] : startA[0];
    const float sty = curve ? startB[1] : startA[1];
    const float dl  = dlp[0];
    float* outc = out + (size_t)curve * (size_t)2 * (size_t)(n + 1);

    const int tid  = threadIdx.x;
    const int lane = tid & 31;
    const int w    = tid >> 5;
    const int base = tile * TILE_N + tid * ITEMS;

    if (tid == 0) {
        float4 p4 = g_pre[curve * TILES + tile];
        float pT = p4.x, pX = p4.y, pY = p4.z;
        float s0, c0, sB, cB;
        sincosf(th0, &s0, &c0);
        sincosf(th0 + pT, &sB, &cB);
        sPre[0] = stx + c0 * pX - s0 * pY;   // bx
        sPre[1] = sty + s0 * pX + c0 * pY;   // by
        sPre[2] = cB;
        sPre[3] = sB;
    }

    float v[ITEMS];
    {
        const float4* v4 = reinterpret_cast<const float4*>(vec + base);
#pragma unroll
        for (int k = 0; k < ITEMS / 4; k++) {
            float4 q = v4[k];
            v[4 * k + 0] = q.x; v[4 * k + 1] = q.y;
            v[4 * k + 2] = q.z; v[4 * k + 3] = q.w;
        }
    }
    float tot = 0.f;
#pragma unroll
    for (int k = 0; k < ITEMS; k += 4)
        tot += (v[k] + v[k + 1]) + (v[k + 2] + v[k + 3]);

    float totT;
    float te = block_escan<NWARP>(tot, sT, totT, tid, lane, w);

    float sn, cs;
    poly_sincos(te, &sn, &cs);
    float zx = dl * cs, zy = dl * sn;
    float Cx = 0.f, Cy = 0.f;
    // curve 0 stages EXCLUSIVE local cumsum, curve 1 INCLUSIVE
#pragma unroll
    for (int k = 0; k < ITEMS; k++) {
        float vk = v[k];
        float ec = fmaf(-0.5f * vk, vk, 1.0f);
        float nx = fmaf(zx, ec, -(zy * vk));
        float ny = fmaf(zy, ec,  (zx * vk));
        zx = nx; zy = ny;
        float px = Cx, py = Cy;
        Cx += zx; Cy += zy;
        sStage[tid * SKEW + k] = curve ? make_float2(Cx, Cy)
                                       : make_float2(px, py);
    }
    float2 tot2;
    float2 e2 = block_escan2<NWARP>(make_float2(Cx, Cy), sXY, tot2, tid, lane, w);
    sExy[tid] = e2;
    __syncthreads();

    const float bx = sPre[0], by = sPre[1], cB = sPre[2], sB = sPre[3];

    float4* dst4 = reinterpret_cast<float4*>(
        outc + 2 * (size_t)tile * TILE_N + (curve ? 2 : 0));
#pragma unroll
    for (int k = 0; k < ITEMS / 2; k++) {
        int p  = k * THREADS + tid;        // float4 index = 2 points
        int wt = p >> 3;
        int kk = (p & 7) * 2;
        float2 l0 = sStage[wt * SKEW + kk];
        float2 l1 = sStage[wt * SKEW + kk + 1];
        float2 e  = sExy[wt];
        float ux0 = e.x + l0.x, uy0 = e.y + l0.y;
        float ux1 = e.x + l1.x, uy1 = e.y + l1.y;
        float4 o;
        o.x = fmaf(cB, ux0, fmaf(-sB, uy0, bx));
        o.y = fmaf(sB, ux0, fmaf( cB, uy0, by));
        o.z = fmaf(cB, ux1, fmaf(-sB, uy1, bx));
        o.w = fmaf(sB, ux1, fmaf( cB, uy1, by));
        stcs4(&dst4[p], o);
    }

    // fix-ups: curve0 last row (N); curve1 first row (0)
    if (curve == 0 && tile == TILES - 1 && tid == THREADS - 1) {
        float ux = e2.x + Cx, uy = e2.y + Cy;
        outc[2 * (size_t)n + 0] = fmaf(cB, ux, fmaf(-sB, uy, bx));
        outc[2 * (size_t)n + 1] = fmaf(sB, ux, fmaf( cB, uy, by));
    }
    if (curve == 1 && tile == 0 && tid == 0) {
        outc[0] = stx; outc[1] = sty;
    }
}

// ---------------- launch ----------------------------------------------------
extern "C" void kernel_launch(void* const* d_in, const int* in_sizes, int n_in,
                              void* d_out, int out_size) {
    const float* vec   = (const float*)d_in[0];
    const float* vec2  = (const float*)d_in[1];
    const float* the0  = (const float*)d_in[2];
    const float* the02 = (const float*)d_in[3];
    const float* PS    = (const float*)d_in[4];
    const float* PE    = (const float*)d_in[5];
    const float* dl    = (const float*)d_in[6];
    float* out = (float*)d_out;

    int n = in_sizes[0];

    cudaFuncSetAttribute(curve_apply_kernel,
                         cudaFuncAttributeMaxDynamicSharedMemorySize, SMEM_BYTES);

    tile_agg_kernel<<<dim3(TILES, 2), THREADS>>>(vec, vec2, dl);
    curve_apply_kernel<<<dim3(TILES, 2), THREADS, SMEM_BYTES>>>(
        vec, vec2, the0, the02, PS, PE, dl, out, n);
}